// round 7
// baseline (speedup 1.0000x reference)
#include <cuda_runtime.h>
#include <math.h>

#define BB 8
#define CC 128
#define HW 128
#define NH 4
#define DH 32
#define PLANE (HW*HW)               // 16384
#define QKV_ELEMS (BB*NH*DH*HW*HW)  // 16,777,216

typedef unsigned long long u64;

// Scratch (device globals: allocation-free)
__device__ float g_q [QKV_ELEMS];
__device__ float g_k [QKV_ELEMS];
__device__ float g_v [QKV_ELEMS];
__device__ float g_qT[QKV_ELEMS];
__device__ float g_kT[QKV_ELEMS];
__device__ float g_vT[QKV_ELEMS];
__device__ float g_a1[BB*CC*HW*HW]; // H-axis out, [b][c][i][j]
__device__ float g_a2[BB*CC*HW*HW]; // W-axis out, [b][c][j][i]
__device__ float g_o [BB*CC*HW*HW]; // post-dwconv

// ---- f32x2 packed math (sm_10x) ----
__device__ __forceinline__ u64 pack2(float lo, float hi) {
    u64 r; asm("mov.b64 %0, {%1, %2};" : "=l"(r) : "f"(lo), "f"(hi)); return r;
}
__device__ __forceinline__ u64 fma2(u64 a, u64 b, u64 c) {
    u64 d; asm("fma.rn.f32x2 %0, %1, %2, %3;" : "=l"(d) : "l"(a), "l"(b), "l"(c)); return d;
}
__device__ __forceinline__ u64 mul2(u64 a, u64 b) {
    u64 d; asm("mul.rn.f32x2 %0, %1, %2;" : "=l"(d) : "l"(a), "l"(b)); return d;
}
__device__ __forceinline__ void unpack2(u64 v, float& lo, float& hi) {
    asm("mov.b64 {%0, %1}, %2;" : "=f"(lo), "=f"(hi) : "l"(v));
}

// ---------------------------------------------------------------------------
// K1: qkv 1x1 conv, split-j for occupancy. One CTA per (b, i, jhalf).
// smem: xs[128][64] (32KB) + wt[128][72] (36KB) = 68KB -> 3 CTAs/SM.
// Thread tile: 4 outputs x 8 j. Writes q/k/v in [b][h][d][i][j].
// ---------------------------------------------------------------------------
__global__ void __launch_bounds__(128, 3) qkv_kernel(const float* __restrict__ x,
                                                     const float* __restrict__ w) {
    extern __shared__ float sm[];
    float* xs = sm;               // xs[c*64 + j]
    float* wt = sm + 128 * 64;    // wt[c*72 + k]
    const int b   = blockIdx.x >> 8;
    const int i   = (blockIdx.x >> 1) & 127;
    const int jh  = blockIdx.x & 1;
    const int tid = threadIdx.x;
    const int ty  = tid >> 3, tx = tid & 7;   // ty 0..15, tx 0..7

    const float* xb = x + (size_t)b * CC * PLANE + (size_t)i * HW + jh * 64;
    for (int idx = tid; idx < CC * 64; idx += 128) {
        int c = idx >> 6, j = idx & 63;
        xs[idx] = xb[(size_t)c * PLANE + j];
    }

    for (int o0 = 0; o0 < 3 * CC; o0 += 64) {
        __syncthreads();
        for (int idx = tid; idx < 64 * 128; idx += 128) {
            int c = idx & 127, k = idx >> 7;
            wt[c * 72 + k] = w[(o0 + k) * CC + c];
        }
        __syncthreads();

        u64 acc[4][4];
        #pragma unroll
        for (int a = 0; a < 4; a++)
            #pragma unroll
            for (int e = 0; e < 4; e++) acc[a][e] = 0ULL;

        for (int c = 0; c < CC; c++) {
            float4 w0 = *(const float4*)&wt[c * 72 + ty * 4];
            ulonglong2 x0 = *(const ulonglong2*)&xs[c * 64 + tx * 8];
            ulonglong2 x1 = *(const ulonglong2*)&xs[c * 64 + tx * 8 + 4];
            u64 xv[4] = {x0.x, x0.y, x1.x, x1.y};
            float wv[4] = {w0.x, w0.y, w0.z, w0.w};
            #pragma unroll
            for (int a = 0; a < 4; a++) {
                u64 wa = pack2(wv[a], wv[a]);
                #pragma unroll
                for (int e = 0; e < 4; e++) acc[a][e] = fma2(wa, xv[e], acc[a][e]);
            }
        }

        #pragma unroll
        for (int a = 0; a < 4; a++) {
            int o    = o0 + ty * 4 + a;
            int t    = o >> 7;
            int head = (o >> 5) & 3;
            int dim  = o & 31;
            float* dst = (t == 0) ? g_q : (t == 1) ? g_k : g_v;
            size_t off = ((((size_t)b * NH + head) * DH + dim) * HW + i) * HW
                       + jh * 64 + tx * 8;
            ulonglong2 s0 = {acc[a][0], acc[a][1]};
            ulonglong2 s1 = {acc[a][2], acc[a][3]};
            *(ulonglong2*)&dst[off]     = s0;
            *(ulonglong2*)&dst[off + 4] = s1;
        }
    }
}

// ---------------------------------------------------------------------------
// K2: transpose (i,j)->(j,i) for every [b][h][d] plane of q/k/v.
// ---------------------------------------------------------------------------
__global__ void __launch_bounds__(256) transpose_kernel() {
    __shared__ float s[32][33];
    int p  = blockIdx.x;
    int t  = p >> 10;
    int pl = p & 1023;
    const float* src = ((t == 0) ? g_q : (t == 1) ? g_k : g_v) + (size_t)pl * PLANE;
    float* dst = ((t == 0) ? g_qT : (t == 1) ? g_kT : g_vT) + (size_t)pl * PLANE;
    int lx = threadIdx.x & 31, ly = threadIdx.x >> 5;

    for (int tile = 0; tile < 16; tile++) {
        int ti = tile >> 2, tj = tile & 3;
        __syncthreads();
        #pragma unroll
        for (int r = 0; r < 32; r += 8)
            s[ly + r][lx] = src[(ti * 32 + ly + r) * HW + tj * 32 + lx];
        __syncthreads();
        #pragma unroll
        for (int r = 0; r < 32; r += 8)
            dst[(tj * 32 + ly + r) * HW + ti * 32 + lx] = s[lx][ly + r];
    }
}

// ---------------------------------------------------------------------------
// K3: axis attention, 2 queries/thread, 2 lines/CTA, d-packed f32x2.
// __launch_bounds__(128,3) caps regs at 168 -> 3 CTAs/SM (12 warps).
// ---------------------------------------------------------------------------
#define VSP 36
__global__ void __launch_bounds__(128, 3) attn_kernel(int which,
                                                      const float* __restrict__ gammap) {
    extern __shared__ float sm[];
    float* dtab = sm;                          // 128
    float* ksb  = sm + 128;                    // 2 * 128*VSP
    float* vsb  = sm + 128 + 2 * 128 * VSP;    // 2 * 128*VSP

    const float* q = which ? g_qT : g_q;
    const float* k = which ? g_kT : g_k;
    const float* v = which ? g_vT : g_v;
    float* out     = which ? g_a2 : g_a1;

    const int bh  = blockIdx.x >> 6;
    const int lp  = blockIdx.x & 63;
    const int tid = threadIdx.x;
    const int l   = tid >> 6;          // which of the 2 lines
    const int u   = tid & 63;
    const int line = 2 * lp + l;
    const int ja = 2 * u, jb = 2 * u + 1;

    dtab[tid & 127] = __expf(-gammap[0] * (float)(tid & 127));

    // fill k/v tiles for both lines, [z][d] layout
    const size_t base0 = (size_t)bh * DH * PLANE + (size_t)(2 * lp) * HW;
    for (int idx = tid; idx < 2 * DH * HW; idx += 128) {
        int ll = idx >> 12;
        int d  = (idx >> 7) & 31;
        int z  = idx & 127;
        size_t g = base0 + (size_t)ll * HW + (size_t)d * PLANE + z;
        ksb[ll * (128 * VSP) + z * VSP + d] = k[g];
        vsb[ll * (128 * VSP) + z * VSP + d] = v[g];
    }

    // q for both queries, packed over d-pairs
    const size_t baseq = (size_t)bh * DH * PLANE + (size_t)line * HW + ja;
    u64 qpa[16], qpb[16];
    #pragma unroll
    for (int dd = 0; dd < 16; dd++) {
        float2 f0 = *(const float2*)&q[baseq + (size_t)(2 * dd)     * PLANE];
        float2 f1 = *(const float2*)&q[baseq + (size_t)(2 * dd + 1) * PLANE];
        qpa[dd] = pack2(f0.x, f1.x);
        qpb[dd] = pack2(f0.y, f1.y);
    }
    __syncthreads();

    const float scale = 0.17677669529663687f; // 32^-0.5
    const float* ksl = ksb + l * (128 * VSP);
    const float* vsl = vsb + l * (128 * VSP);

    float s_a = 0.f, s_b = 0.f;
    u64 acc_a[16], acc_b[16];
    #pragma unroll
    for (int t = 0; t < 16; t++) { acc_a[t] = 0ULL; acc_b[t] = 0ULL; }

    #pragma unroll 1
    for (int z0 = 0; z0 < 128; z0 += 4) {
        float sa[4], sb[4];
        #pragma unroll
        for (int zz = 0; zz < 4; zz++) {
            const ulonglong2* kp = (const ulonglong2*)&ksl[(z0 + zz) * VSP];
            u64 aa = 0ULL, ab = 0ULL;
            #pragma unroll
            for (int t = 0; t < 8; t++) {
                ulonglong2 kk = kp[t];
                aa = fma2(qpa[2 * t],     kk.x, aa);
                aa = fma2(qpa[2 * t + 1], kk.y, aa);
                ab = fma2(qpb[2 * t],     kk.x, ab);
                ab = fma2(qpb[2 * t + 1], kk.y, ab);
            }
            float lo, hi;
            unpack2(aa, lo, hi); sa[zz] = (lo + hi) * scale;
            unpack2(ab, lo, hi); sb[zz] = (lo + hi) * scale;
        }
        #pragma unroll
        for (int zz = 0; zz < 4; zz++) {
            int z = z0 + zz;
            float ea = __expf(sa[zz]); s_a += ea;
            float eb = __expf(sb[zz]); s_b += eb;
            int da = (ja > z) ? (ja - z) : (z - ja);
            int db = (jb > z) ? (jb - z) : (z - jb);
            float pa = ea * dtab[da];
            float pb = eb * dtab[db];
            u64 pa2 = pack2(pa, pa), pb2 = pack2(pb, pb);
            const ulonglong2* vp = (const ulonglong2*)&vsl[z * VSP];
            #pragma unroll
            for (int t = 0; t < 8; t++) {
                ulonglong2 vv = vp[t];
                acc_a[2 * t]     = fma2(pa2, vv.x, acc_a[2 * t]);
                acc_a[2 * t + 1] = fma2(pa2, vv.y, acc_a[2 * t + 1]);
                acc_b[2 * t]     = fma2(pb2, vv.x, acc_b[2 * t]);
                acc_b[2 * t + 1] = fma2(pb2, vv.y, acc_b[2 * t + 1]);
            }
        }
    }

    u64 rs2 = pack2(1.0f / s_a, 1.0f / s_b);
    const int b = bh >> 2, h = bh & 3;
    #pragma unroll
    for (int dd = 0; dd < 16; dd++) {
        float alo, ahi, blo, bhi;
        unpack2(acc_a[dd], alo, ahi);
        unpack2(acc_b[dd], blo, bhi);
        u64 v0 = mul2(pack2(alo, blo), rs2);     // d = 2dd,   j = ja..jb
        u64 v1 = mul2(pack2(ahi, bhi), rs2);     // d = 2dd+1
        size_t o0 = ((((size_t)b * CC + h * DH + 2 * dd) * HW + line) * HW) + ja;
        *(u64*)&out[o0]          = v0;
        *(u64*)&out[o0 + PLANE]  = v1;
    }
}

// ---------------------------------------------------------------------------
// K4: combined = a1 + a2^T, then depthwise 3x3 SAME conv -> g_o.
// ---------------------------------------------------------------------------
__global__ void __launch_bounds__(256) dw_kernel(const float* __restrict__ wdw) {
    extern __shared__ float sm[]; // 130*130
    const int bc = blockIdx.x;
    const int c  = bc & 127;
    const int tid = threadIdx.x;
    const float* p1 = g_a1 + (size_t)bc * PLANE;
    const float* p2 = g_a2 + (size_t)bc * PLANE;
    float* po       = g_o  + (size_t)bc * PLANE;

    for (int idx = tid; idx < 130 * 130; idx += 256) sm[idx] = 0.f;
    __syncthreads();
    for (int idx = tid; idx < PLANE; idx += 256) {
        int i = idx >> 7, j = idx & 127;
        sm[(i + 1) * 130 + (j + 1)] = p1[idx];
    }
    __syncthreads();
    for (int idx = tid; idx < PLANE; idx += 256) {
        int j = idx >> 7, i = idx & 127;     // a2 is [j][i]
        sm[(i + 1) * 130 + (j + 1)] += p2[idx];
    }
    __syncthreads();

    float w[9];
    #pragma unroll
    for (int t = 0; t < 9; t++) w[t] = wdw[c * 9 + t];

    for (int idx = tid; idx < PLANE; idx += 256) {
        int i = idx >> 7, j = idx & 127;
        const float* r0 = &sm[i * 130 + j];
        float acc = w[0] * r0[0]   + w[1] * r0[1]   + w[2] * r0[2]
                  + w[3] * r0[130] + w[4] * r0[131] + w[5] * r0[132]
                  + w[6] * r0[260] + w[7] * r0[261] + w[8] * r0[262];
        po[idx] = acc;
    }
}

// ---------------------------------------------------------------------------
// K5: 1x1 proj GEMM, split-j (same structure as K1). Output [b][o][i][j].
// ---------------------------------------------------------------------------
__global__ void __launch_bounds__(128, 3) proj_kernel(const float* __restrict__ w,
                                                      float* __restrict__ out) {
    extern __shared__ float sm[];
    float* xs = sm;               // xs[c*64 + j]
    float* wt = sm + 128 * 64;    // wt[c*72 + k]
    const int b   = blockIdx.x >> 8;
    const int i   = (blockIdx.x >> 1) & 127;
    const int jh  = blockIdx.x & 1;
    const int tid = threadIdx.x;
    const int ty  = tid >> 3, tx = tid & 7;

    const float* xb = g_o + (size_t)b * CC * PLANE + (size_t)i * HW + jh * 64;
    for (int idx = tid; idx < CC * 64; idx += 128) {
        int c = idx >> 6, j = idx & 63;
        xs[idx] = xb[(size_t)c * PLANE + j];
    }

    for (int o0 = 0; o0 < CC; o0 += 64) {
        __syncthreads();
        for (int idx = tid; idx < 64 * 128; idx += 128) {
            int c = idx & 127, kk = idx >> 7;
            wt[c * 72 + kk] = w[(o0 + kk) * CC + c];
        }
        __syncthreads();

        u64 acc[4][4];
        #pragma unroll
        for (int a = 0; a < 4; a++)
            #pragma unroll
            for (int e = 0; e < 4; e++) acc[a][e] = 0ULL;

        for (int c = 0; c < CC; c++) {
            float4 w0 = *(const float4*)&wt[c * 72 + ty * 4];
            ulonglong2 x0 = *(const ulonglong2*)&xs[c * 64 + tx * 8];
            ulonglong2 x1 = *(const ulonglong2*)&xs[c * 64 + tx * 8 + 4];
            u64 xv[4] = {x0.x, x0.y, x1.x, x1.y};
            float wv[4] = {w0.x, w0.y, w0.z, w0.w};
            #pragma unroll
            for (int a = 0; a < 4; a++) {
                u64 wa = pack2(wv[a], wv[a]);
                #pragma unroll
                for (int e = 0; e < 4; e++) acc[a][e] = fma2(wa, xv[e], acc[a][e]);
            }
        }

        #pragma unroll
        for (int a = 0; a < 4; a++) {
            int o = o0 + ty * 4 + a;
            size_t off = ((size_t)(b * CC + o) * HW + i) * HW + jh * 64 + tx * 8;
            ulonglong2 s0 = {acc[a][0], acc[a][1]};
            ulonglong2 s1 = {acc[a][2], acc[a][3]};
            *(ulonglong2*)&out[off]     = s0;
            *(ulonglong2*)&out[off + 4] = s1;
        }
    }
}

// ---------------------------------------------------------------------------
extern "C" void kernel_launch(void* const* d_in, const int* in_sizes, int n_in,
                              void* d_out, int out_size) {
    (void)in_sizes; (void)n_in; (void)out_size;
    const float* x     = (const float*)d_in[0];
    const float* wqkv  = (const float*)d_in[1];
    const float* wproj = (const float*)d_in[2];
    const float* wdw   = (const float*)d_in[3];
    const float* gamma = (const float*)d_in[4];
    float* out = (float*)d_out;

    const int SM_GEMM = (128 * 64 + 128 * 72) * 4;           // 69632
    const int SM_ATTN = (128 + 4 * 128 * VSP) * 4;           // 74240
    const int SM_DW   = 130 * 130 * 4;                       // 67600

    cudaFuncSetAttribute(qkv_kernel,  cudaFuncAttributeMaxDynamicSharedMemorySize, SM_GEMM);
    cudaFuncSetAttribute(attn_kernel, cudaFuncAttributeMaxDynamicSharedMemorySize, SM_ATTN);
    cudaFuncSetAttribute(dw_kernel,   cudaFuncAttributeMaxDynamicSharedMemorySize, SM_DW);
    cudaFuncSetAttribute(proj_kernel, cudaFuncAttributeMaxDynamicSharedMemorySize, SM_GEMM);

    qkv_kernel<<<BB * HW * 2, 128, SM_GEMM>>>(x, wqkv);
    transpose_kernel<<<3 * BB * NH * DH, 256>>>();
    attn_kernel<<<BB * NH * HW / 2, 128, SM_ATTN>>>(0, gamma);
    attn_kernel<<<BB * NH * HW / 2, 128, SM_ATTN>>>(1, gamma);
    dw_kernel<<<BB * CC, 256, SM_DW>>>(wdw);
    proj_kernel<<<BB * HW * 2, 128, SM_GEMM>>>(wproj, out);
}

// round 8
// speedup vs baseline: 1.2802x; 1.2802x over previous
#include <cuda_runtime.h>
#include <math.h>

#define BB 8
#define CC 128
#define HW 128
#define NH 4
#define DH 32
#define PLANE (HW*HW)               // 16384
#define QKV_ELEMS (BB*NH*DH*HW*HW)  // 16,777,216
#define WTP 68                      // wt row stride (mult of 4 words for u64x2 loads)

typedef unsigned long long u64;

// Scratch (device globals: allocation-free)
__device__ float g_q [QKV_ELEMS];
__device__ float g_k [QKV_ELEMS];
__device__ float g_v [QKV_ELEMS];
__device__ float g_qT[QKV_ELEMS];
__device__ float g_kT[QKV_ELEMS];
__device__ float g_vT[QKV_ELEMS];
__device__ float g_a1[BB*CC*HW*HW]; // H-axis out, [b][c][i][j]
__device__ float g_a2[BB*CC*HW*HW]; // W-axis out, [b][c][j][i]
__device__ float g_o [BB*CC*HW*HW]; // post-dwconv

// ---- f32x2 packed math (sm_10x) ----
__device__ __forceinline__ u64 pack2(float lo, float hi) {
    u64 r; asm("mov.b64 %0, {%1, %2};" : "=l"(r) : "f"(lo), "f"(hi)); return r;
}
__device__ __forceinline__ u64 fma2(u64 a, u64 b, u64 c) {
    u64 d; asm("fma.rn.f32x2 %0, %1, %2, %3;" : "=l"(d) : "l"(a), "l"(b), "l"(c)); return d;
}
__device__ __forceinline__ u64 mul2(u64 a, u64 b) {
    u64 d; asm("mul.rn.f32x2 %0, %1, %2;" : "=l"(d) : "l"(a), "l"(b)); return d;
}
__device__ __forceinline__ void unpack2(u64 v, float& lo, float& hi) {
    asm("mov.b64 {%0, %1}, %2;" : "=f"(lo), "=f"(hi) : "l"(v));
}

// ---------------------------------------------------------------------------
// K1: qkv 1x1 conv. One CTA (256 thr) per (b, i). 2 CTAs/SM (100KB smem).
// Block tile per chunk: 64 outputs x 128 j. Thread tile 8o x 4j,
// acc packed over o-pairs (weights load as u64 pairs, no splat).
// Writes q/k/v in [b][h][d][i][j].
// ---------------------------------------------------------------------------
__global__ void __launch_bounds__(256, 2) qkv_kernel(const float* __restrict__ x,
                                                     const float* __restrict__ w) {
    extern __shared__ float sm[];
    float* xs = sm;               // xs[c*128 + j]
    float* wt = sm + 16384;       // wt[c*WTP + k], k<64
    const int b   = blockIdx.x >> 7;
    const int i   = blockIdx.x & 127;
    const int tid = threadIdx.x;
    const int ty  = tid >> 5;     // 0..7  -> o-group of 8
    const int tx  = tid & 31;     // 0..31 -> j-group of 4

    const float* xb = x + (size_t)b * CC * PLANE + (size_t)i * HW;
    for (int idx = tid; idx < CC * HW; idx += 256) {
        int c = idx >> 7, j = idx & 127;
        xs[idx] = xb[(size_t)c * PLANE + j];
    }

    for (int o0 = 0; o0 < 3 * CC; o0 += 64) {
        __syncthreads();
        for (int idx = tid; idx < 64 * 128; idx += 256) {
            int c = idx & 127, k = idx >> 7;
            wt[c * WTP + k] = w[(o0 + k) * CC + c];
        }
        __syncthreads();

        u64 acc[4][4];   // [o-pair][j]
        #pragma unroll
        for (int a = 0; a < 4; a++)
            #pragma unroll
            for (int e = 0; e < 4; e++) acc[a][e] = 0ULL;

        for (int c = 0; c < CC; c++) {
            ulonglong2 wA = *(const ulonglong2*)&wt[c * WTP + ty * 8];
            ulonglong2 wB = *(const ulonglong2*)&wt[c * WTP + ty * 8 + 4];
            float4 xf = *(const float4*)&xs[c * 128 + tx * 4];
            u64 wv[4] = {wA.x, wA.y, wB.x, wB.y};
            u64 xv[4] = {pack2(xf.x, xf.x), pack2(xf.y, xf.y),
                         pack2(xf.z, xf.z), pack2(xf.w, xf.w)};
            #pragma unroll
            for (int a = 0; a < 4; a++)
                #pragma unroll
                for (int e = 0; e < 4; e++) acc[a][e] = fma2(wv[a], xv[e], acc[a][e]);
        }

        #pragma unroll
        for (int a = 0; a < 4; a++) {
            float e0lo, e0hi, e1lo, e1hi, e2lo, e2hi, e3lo, e3hi;
            unpack2(acc[a][0], e0lo, e0hi);
            unpack2(acc[a][1], e1lo, e1hi);
            unpack2(acc[a][2], e2lo, e2hi);
            unpack2(acc[a][3], e3lo, e3hi);
            int oe = o0 + ty * 8 + 2 * a;
            #pragma unroll
            for (int par = 0; par < 2; par++) {
                int o = oe + par;
                float4 row = par ? make_float4(e0hi, e1hi, e2hi, e3hi)
                                 : make_float4(e0lo, e1lo, e2lo, e3lo);
                int t    = o >> 7;
                int head = (o >> 5) & 3;
                int dim  = o & 31;
                float* dst = (t == 0) ? g_q : (t == 1) ? g_k : g_v;
                size_t off = ((((size_t)b * NH + head) * DH + dim) * HW + i) * HW + tx * 4;
                *(float4*)&dst[off] = row;
            }
        }
    }
}

// ---------------------------------------------------------------------------
// K2: transpose (i,j)->(j,i) for every [b][h][d] plane of q/k/v.
// ---------------------------------------------------------------------------
__global__ void __launch_bounds__(256) transpose_kernel() {
    __shared__ float s[32][33];
    int p  = blockIdx.x;
    int t  = p >> 10;
    int pl = p & 1023;
    const float* src = ((t == 0) ? g_q : (t == 1) ? g_k : g_v) + (size_t)pl * PLANE;
    float* dst = ((t == 0) ? g_qT : (t == 1) ? g_kT : g_vT) + (size_t)pl * PLANE;
    int lx = threadIdx.x & 31, ly = threadIdx.x >> 5;

    for (int tile = 0; tile < 16; tile++) {
        int ti = tile >> 2, tj = tile & 3;
        __syncthreads();
        #pragma unroll
        for (int r = 0; r < 32; r += 8)
            s[ly + r][lx] = src[(ti * 32 + ly + r) * HW + tj * 32 + lx];
        __syncthreads();
        #pragma unroll
        for (int r = 0; r < 32; r += 8)
            dst[(tj * 32 + ly + r) * HW + ti * 32 + lx] = s[lx][ly + r];
    }
}

// ---------------------------------------------------------------------------
// K3: axis attention, 2 queries/thread, 2 lines/CTA, d-packed f32x2.
// (R6 version: uncapped regs, 2 CTAs/SM.)
// ---------------------------------------------------------------------------
#define VSP 36
__global__ void __launch_bounds__(128) attn_kernel(int which,
                                                   const float* __restrict__ gammap) {
    extern __shared__ float sm[];
    float* dtab = sm;                          // 128
    float* ksb  = sm + 128;                    // 2 * 128*VSP
    float* vsb  = sm + 128 + 2 * 128 * VSP;    // 2 * 128*VSP

    const float* q = which ? g_qT : g_q;
    const float* k = which ? g_kT : g_k;
    const float* v = which ? g_vT : g_v;
    float* out     = which ? g_a2 : g_a1;

    const int bh  = blockIdx.x >> 6;
    const int lp  = blockIdx.x & 63;
    const int tid = threadIdx.x;
    const int l   = tid >> 6;          // which of the 2 lines
    const int u   = tid & 63;
    const int line = 2 * lp + l;
    const int ja = 2 * u, jb = 2 * u + 1;

    dtab[tid & 127] = __expf(-gammap[0] * (float)(tid & 127));

    // fill k/v tiles for both lines, [z][d] layout
    const size_t base0 = (size_t)bh * DH * PLANE + (size_t)(2 * lp) * HW;
    for (int idx = tid; idx < 2 * DH * HW; idx += 128) {
        int ll = idx >> 12;
        int d  = (idx >> 7) & 31;
        int z  = idx & 127;
        size_t g = base0 + (size_t)ll * HW + (size_t)d * PLANE + z;
        ksb[ll * (128 * VSP) + z * VSP + d] = k[g];
        vsb[ll * (128 * VSP) + z * VSP + d] = v[g];
    }

    // q for both queries, packed over d-pairs
    const size_t baseq = (size_t)bh * DH * PLANE + (size_t)line * HW + ja;
    u64 qpa[16], qpb[16];
    #pragma unroll
    for (int dd = 0; dd < 16; dd++) {
        float2 f0 = *(const float2*)&q[baseq + (size_t)(2 * dd)     * PLANE];
        float2 f1 = *(const float2*)&q[baseq + (size_t)(2 * dd + 1) * PLANE];
        qpa[dd] = pack2(f0.x, f1.x);
        qpb[dd] = pack2(f0.y, f1.y);
    }
    __syncthreads();

    const float scale = 0.17677669529663687f; // 32^-0.5
    const float* ksl = ksb + l * (128 * VSP);
    const float* vsl = vsb + l * (128 * VSP);

    float s_a = 0.f, s_b = 0.f;
    u64 acc_a[16], acc_b[16];
    #pragma unroll
    for (int t = 0; t < 16; t++) { acc_a[t] = 0ULL; acc_b[t] = 0ULL; }

    #pragma unroll 1
    for (int z0 = 0; z0 < 128; z0 += 4) {
        float sa[4], sb[4];
        #pragma unroll
        for (int zz = 0; zz < 4; zz++) {
            const ulonglong2* kp = (const ulonglong2*)&ksl[(z0 + zz) * VSP];
            u64 aa = 0ULL, ab = 0ULL;
            #pragma unroll
            for (int t = 0; t < 8; t++) {
                ulonglong2 kk = kp[t];
                aa = fma2(qpa[2 * t],     kk.x, aa);
                aa = fma2(qpa[2 * t + 1], kk.y, aa);
                ab = fma2(qpb[2 * t],     kk.x, ab);
                ab = fma2(qpb[2 * t + 1], kk.y, ab);
            }
            float lo, hi;
            unpack2(aa, lo, hi); sa[zz] = (lo + hi) * scale;
            unpack2(ab, lo, hi); sb[zz] = (lo + hi) * scale;
        }
        #pragma unroll
        for (int zz = 0; zz < 4; zz++) {
            int z = z0 + zz;
            float ea = __expf(sa[zz]); s_a += ea;
            float eb = __expf(sb[zz]); s_b += eb;
            int da = (ja > z) ? (ja - z) : (z - ja);
            int db = (jb > z) ? (jb - z) : (z - jb);
            float pa = ea * dtab[da];
            float pb = eb * dtab[db];
            u64 pa2 = pack2(pa, pa), pb2 = pack2(pb, pb);
            const ulonglong2* vp = (const ulonglong2*)&vsl[z * VSP];
            #pragma unroll
            for (int t = 0; t < 8; t++) {
                ulonglong2 vv = vp[t];
                acc_a[2 * t]     = fma2(pa2, vv.x, acc_a[2 * t]);
                acc_a[2 * t + 1] = fma2(pa2, vv.y, acc_a[2 * t + 1]);
                acc_b[2 * t]     = fma2(pb2, vv.x, acc_b[2 * t]);
                acc_b[2 * t + 1] = fma2(pb2, vv.y, acc_b[2 * t + 1]);
            }
        }
    }

    u64 rs2 = pack2(1.0f / s_a, 1.0f / s_b);
    const int b = bh >> 2, h = bh & 3;
    #pragma unroll
    for (int dd = 0; dd < 16; dd++) {
        float alo, ahi, blo, bhi;
        unpack2(acc_a[dd], alo, ahi);
        unpack2(acc_b[dd], blo, bhi);
        u64 v0 = mul2(pack2(alo, blo), rs2);     // d = 2dd,   j = ja..jb
        u64 v1 = mul2(pack2(ahi, bhi), rs2);     // d = 2dd+1
        size_t o0 = ((((size_t)b * CC + h * DH + 2 * dd) * HW + line) * HW) + ja;
        *(u64*)&out[o0]          = v0;
        *(u64*)&out[o0 + PLANE]  = v1;
    }
}

// ---------------------------------------------------------------------------
// K4: combined = a1 + a2^T, then depthwise 3x3 SAME conv -> g_o.
// ---------------------------------------------------------------------------
__global__ void __launch_bounds__(256) dw_kernel(const float* __restrict__ wdw) {
    extern __shared__ float sm[]; // 130*130
    const int bc = blockIdx.x;
    const int c  = bc & 127;
    const int tid = threadIdx.x;
    const float* p1 = g_a1 + (size_t)bc * PLANE;
    const float* p2 = g_a2 + (size_t)bc * PLANE;
    float* po       = g_o  + (size_t)bc * PLANE;

    for (int idx = tid; idx < 130 * 130; idx += 256) sm[idx] = 0.f;
    __syncthreads();
    for (int idx = tid; idx < PLANE; idx += 256) {
        int i = idx >> 7, j = idx & 127;
        sm[(i + 1) * 130 + (j + 1)] = p1[idx];
    }
    __syncthreads();
    for (int idx = tid; idx < PLANE; idx += 256) {
        int j = idx >> 7, i = idx & 127;     // a2 is [j][i]
        sm[(i + 1) * 130 + (j + 1)] += p2[idx];
    }
    __syncthreads();

    float w[9];
    #pragma unroll
    for (int t = 0; t < 9; t++) w[t] = wdw[c * 9 + t];

    for (int idx = tid; idx < PLANE; idx += 256) {
        int i = idx >> 7, j = idx & 127;
        const float* r0 = &sm[i * 130 + j];
        float acc = w[0] * r0[0]   + w[1] * r0[1]   + w[2] * r0[2]
                  + w[3] * r0[130] + w[4] * r0[131] + w[5] * r0[132]
                  + w[6] * r0[260] + w[7] * r0[261] + w[8] * r0[262];
        po[idx] = acc;
    }
}

// ---------------------------------------------------------------------------
// K5: 1x1 proj GEMM, same structure as K1. Output [b][o][i][j] to d_out.
// ---------------------------------------------------------------------------
__global__ void __launch_bounds__(256, 2) proj_kernel(const float* __restrict__ w,
                                                      float* __restrict__ out) {
    extern __shared__ float sm[];
    float* xs = sm;
    float* wt = sm + 16384;
    const int b   = blockIdx.x >> 7;
    const int i   = blockIdx.x & 127;
    const int tid = threadIdx.x;
    const int ty  = tid >> 5;
    const int tx  = tid & 31;

    const float* xb = g_o + (size_t)b * CC * PLANE + (size_t)i * HW;
    for (int idx = tid; idx < CC * HW; idx += 256) {
        int c = idx >> 7, j = idx & 127;
        xs[idx] = xb[(size_t)c * PLANE + j];
    }

    for (int o0 = 0; o0 < CC; o0 += 64) {
        __syncthreads();
        for (int idx = tid; idx < 64 * 128; idx += 256) {
            int c = idx & 127, k = idx >> 7;
            wt[c * WTP + k] = w[(o0 + k) * CC + c];
        }
        __syncthreads();

        u64 acc[4][4];
        #pragma unroll
        for (int a = 0; a < 4; a++)
            #pragma unroll
            for (int e = 0; e < 4; e++) acc[a][e] = 0ULL;

        for (int c = 0; c < CC; c++) {
            ulonglong2 wA = *(const ulonglong2*)&wt[c * WTP + ty * 8];
            ulonglong2 wB = *(const ulonglong2*)&wt[c * WTP + ty * 8 + 4];
            float4 xf = *(const float4*)&xs[c * 128 + tx * 4];
            u64 wv[4] = {wA.x, wA.y, wB.x, wB.y};
            u64 xv[4] = {pack2(xf.x, xf.x), pack2(xf.y, xf.y),
                         pack2(xf.z, xf.z), pack2(xf.w, xf.w)};
            #pragma unroll
            for (int a = 0; a < 4; a++)
                #pragma unroll
                for (int e = 0; e < 4; e++) acc[a][e] = fma2(wv[a], xv[e], acc[a][e]);
        }

        #pragma unroll
        for (int a = 0; a < 4; a++) {
            float e0lo, e0hi, e1lo, e1hi, e2lo, e2hi, e3lo, e3hi;
            unpack2(acc[a][0], e0lo, e0hi);
            unpack2(acc[a][1], e1lo, e1hi);
            unpack2(acc[a][2], e2lo, e2hi);
            unpack2(acc[a][3], e3lo, e3hi);
            int oe = o0 + ty * 8 + 2 * a;
            #pragma unroll
            for (int par = 0; par < 2; par++) {
                int o = oe + par;
                float4 row = par ? make_float4(e0hi, e1hi, e2hi, e3hi)
                                 : make_float4(e0lo, e1lo, e2lo, e3lo);
                size_t off = ((size_t)(b * CC + o) * HW + i) * HW + tx * 4;
                *(float4*)&out[off] = row;
            }
        }
    }
}

// ---------------------------------------------------------------------------
extern "C" void kernel_launch(void* const* d_in, const int* in_sizes, int n_in,
                              void* d_out, int out_size) {
    (void)in_sizes; (void)n_in; (void)out_size;
    const float* x     = (const float*)d_in[0];
    const float* wqkv  = (const float*)d_in[1];
    const float* wproj = (const float*)d_in[2];
    const float* wdw   = (const float*)d_in[3];
    const float* gamma = (const float*)d_in[4];
    float* out = (float*)d_out;

    const int SM_GEMM = (16384 + 128 * WTP) * 4;             // 100352
    const int SM_ATTN = (128 + 4 * 128 * VSP) * 4;           // 74240
    const int SM_DW   = 130 * 130 * 4;                       // 67600

    cudaFuncSetAttribute(qkv_kernel,  cudaFuncAttributeMaxDynamicSharedMemorySize, SM_GEMM);
    cudaFuncSetAttribute(attn_kernel, cudaFuncAttributeMaxDynamicSharedMemorySize, SM_ATTN);
    cudaFuncSetAttribute(dw_kernel,   cudaFuncAttributeMaxDynamicSharedMemorySize, SM_DW);
    cudaFuncSetAttribute(proj_kernel, cudaFuncAttributeMaxDynamicSharedMemorySize, SM_GEMM);

    qkv_kernel<<<BB * HW, 256, SM_GEMM>>>(x, wqkv);
    transpose_kernel<<<3 * BB * NH * DH, 256>>>();
    attn_kernel<<<BB * NH * HW / 2, 128, SM_ATTN>>>(0, gamma);
    attn_kernel<<<BB * NH * HW / 2, 128, SM_ATTN>>>(1, gamma);
    dw_kernel<<<BB * CC, 256, SM_DW>>>(wdw);
    proj_kernel<<<BB * HW, 256, SM_GEMM>>>(wproj, out);
}